// round 4
// baseline (speedup 1.0000x reference)
#include <cuda_runtime.h>

// Wilson Dslash, 32^4, DeGrand-Rossi, half-spinor trick.
// R4: 2D tile (x3=32, x2=8) per 256-thread block; psi staged in smem
// (tile + periodic x2 halo) so x2/x3 neighbor reads avoid L2.

static constexpr int VOL = 1 << 20;

template<int A>
__device__ __forceinline__ void load9(const float* __restrict__ p, float* v) {
    if (A == 0) {
        float4 a = __ldg((const float4*)p);
        float4 b = __ldg((const float4*)(p + 4));
        v[0]=a.x; v[1]=a.y; v[2]=a.z; v[3]=a.w;
        v[4]=b.x; v[5]=b.y; v[6]=b.z; v[7]=b.w;
        v[8]=__ldg(p + 8);
    } else if (A == 4) {
        v[0]=__ldg(p);
        float2 c = __ldg((const float2*)(p + 1));
        float4 d = __ldg((const float4*)(p + 3));
        float2 e = __ldg((const float2*)(p + 7));
        v[1]=c.x; v[2]=c.y; v[3]=d.x; v[4]=d.y; v[5]=d.z; v[6]=d.w;
        v[7]=e.x; v[8]=e.y;
    } else if (A == 8) {
        float2 a = __ldg((const float2*)p);
        float4 b = __ldg((const float4*)(p + 2));
        float2 c = __ldg((const float2*)(p + 6));
        v[0]=a.x; v[1]=a.y; v[2]=b.x; v[3]=b.y; v[4]=b.z; v[5]=b.w;
        v[6]=c.x; v[7]=c.y; v[8]=__ldg(p + 8);
    } else {
        v[0]=__ldg(p);
        float4 b = __ldg((const float4*)(p + 1));
        float4 c = __ldg((const float4*)(p + 5));
        v[1]=b.x; v[2]=b.y; v[3]=b.z; v[4]=b.w;
        v[5]=c.x; v[6]=c.y; v[7]=c.z; v[8]=c.w;
    }
}

__device__ __forceinline__ void load12g(const float* __restrict__ p, float* v) {
    float4 a = __ldg((const float4*)p);
    float4 b = __ldg((const float4*)(p + 4));
    float4 c = __ldg((const float4*)(p + 8));
    v[0]=a.x; v[1]=a.y; v[2]=a.z;  v[3]=a.w;
    v[4]=b.x; v[5]=b.y; v[6]=b.z;  v[7]=b.w;
    v[8]=c.x; v[9]=c.y; v[10]=c.z; v[11]=c.w;
}

// smem read: 48B site stride, 16B-aligned base -> conflict-free LDS.128
__device__ __forceinline__ void load12s(const float* p, float* v) {
    float4 a = *(const float4*)p;
    float4 b = *(const float4*)(p + 4);
    float4 c = *(const float4*)(p + 8);
    v[0]=a.x; v[1]=a.y; v[2]=a.z;  v[3]=a.w;
    v[4]=b.x; v[5]=b.y; v[6]=b.z;  v[7]=b.w;
    v[8]=c.x; v[9]=c.y; v[10]=c.z; v[11]=c.w;
}

// Core: psi already in Pr/Pi, U loaded with alignment A.
template<int MU, bool DAG>
__device__ __forceinline__ void term_core(
    const float* Pr, const float* Pi,
    const float* __restrict__ ur, const float* __restrict__ ui,
    float* ar, float* ai)
{
    constexpr int A = (MU * 36) & 15;
    float Ur[9], Ui[9];
    load9<A>(ur, Ur);
    load9<A>(ui, Ui);

    float hr[6], hi[6];
#pragma unroll
    for (int c = 0; c < 3; c++) {
        float p0r = Pr[c],     p0i = Pi[c];
        float p1r = Pr[3 + c], p1i = Pi[3 + c];
        float p2r = Pr[6 + c], p2i = Pi[6 + c];
        float p3r = Pr[9 + c], p3i = Pi[9 + c];
        float h0r, h0i, h1r, h1i;
        if (MU == 0) {
            if (!DAG) { h0r = p0r + p3i; h0i = p0i - p3r; h1r = p1r + p2i; h1i = p1i - p2r; }
            else      { h0r = p0r - p3i; h0i = p0i + p3r; h1r = p1r - p2i; h1i = p1i + p2r; }
        } else if (MU == 1) {
            if (!DAG) { h0r = p0r + p3r; h0i = p0i + p3i; h1r = p1r - p2r; h1i = p1i - p2i; }
            else      { h0r = p0r - p3r; h0i = p0i - p3i; h1r = p1r + p2r; h1i = p1i + p2i; }
        } else if (MU == 2) {
            if (!DAG) { h0r = p0r + p2i; h0i = p0i - p2r; h1r = p1r - p3i; h1i = p1i + p3r; }
            else      { h0r = p0r - p2i; h0i = p0i + p2r; h1r = p1r + p3i; h1i = p1i - p3r; }
        } else {
            if (!DAG) { h0r = p0r - p2r; h0i = p0i - p2i; h1r = p1r - p3r; h1i = p1i - p3i; }
            else      { h0r = p0r + p2r; h0i = p0i + p2i; h1r = p1r + p3r; h1i = p1i + p3i; }
        }
        hr[c] = h0r; hi[c] = h0i; hr[3 + c] = h1r; hi[3 + c] = h1i;
    }

    float gr[6], gi[6];
#pragma unroll
    for (int s = 0; s < 2; s++) {
#pragma unroll
        for (int i = 0; i < 3; i++) {
            float rr = 0.f, ii = 0.f;
#pragma unroll
            for (int j = 0; j < 3; j++) {
                float urv, uiv;
                if (!DAG) { urv = Ur[i * 3 + j]; uiv = Ui[i * 3 + j]; }
                else      { urv = Ur[j * 3 + i]; uiv = -Ui[j * 3 + i]; }
                rr += urv * hr[s * 3 + j] - uiv * hi[s * 3 + j];
                ii += urv * hi[s * 3 + j] + uiv * hr[s * 3 + j];
            }
            gr[s * 3 + i] = rr; gi[s * 3 + i] = ii;
        }
    }

#pragma unroll
    for (int c = 0; c < 3; c++) {
        ar[c]     += gr[c];     ai[c]     += gi[c];
        ar[3 + c] += gr[3 + c]; ai[3 + c] += gi[3 + c];
        if (MU == 0) {
            if (!DAG) { ar[6+c] -= gi[3+c]; ai[6+c] += gr[3+c]; ar[9+c] -= gi[c]; ai[9+c] += gr[c]; }
            else      { ar[6+c] += gi[3+c]; ai[6+c] -= gr[3+c]; ar[9+c] += gi[c]; ai[9+c] -= gr[c]; }
        } else if (MU == 1) {
            if (!DAG) { ar[6+c] -= gr[3+c]; ai[6+c] -= gi[3+c]; ar[9+c] += gr[c]; ai[9+c] += gi[c]; }
            else      { ar[6+c] += gr[3+c]; ai[6+c] += gi[3+c]; ar[9+c] -= gr[c]; ai[9+c] -= gi[c]; }
        } else if (MU == 2) {
            if (!DAG) { ar[6+c] -= gi[c]; ai[6+c] += gr[c]; ar[9+c] += gi[3+c]; ai[9+c] -= gr[3+c]; }
            else      { ar[6+c] += gi[c]; ai[6+c] -= gr[c]; ar[9+c] -= gi[3+c]; ai[9+c] += gr[3+c]; }
        } else {
            if (!DAG) { ar[6+c] -= gr[c]; ai[6+c] -= gi[c]; ar[9+c] -= gr[3+c]; ai[9+c] -= gi[3+c]; }
            else      { ar[6+c] += gr[c]; ai[6+c] += gi[c]; ar[9+c] += gr[3+c]; ai[9+c] += gi[3+c]; }
        }
    }
}

__global__ void __launch_bounds__(256) wilson_dslash_kernel(
    const float* __restrict__ psi_re, const float* __restrict__ psi_im,
    const float* __restrict__ U_re,   const float* __restrict__ U_im,
    float* __restrict__ out_re, float* __restrict__ out_im)
{
    // smem: 10 x2-rows (tile of 8 + halo row below/above), 32 x3-sites, 12 floats
    __shared__ float s_re[10 * 32 * 12];
    __shared__ float s_im[10 * 32 * 12];

    const int tx = threadIdx.x & 31;       // x3
    const int ty = threadIdx.x >> 5;       // x2 within tile (0..7)
    const int b  = blockIdx.x;
    const int x2b = (b & 3) << 3;
    const int x1  = (b >> 2) & 31;
    const int x0  = b >> 7;

    // Stage psi rows x2b-1 .. x2b+8 (periodic)
    for (int s = threadIdx.x; s < 320; s += 256) {
        int row = s >> 5, x3s = s & 31;
        int x2s = (x2b + row + 31) & 31;
        size_t g = (size_t)((x0 << 15) | (x1 << 10) | (x2s << 5) | x3s) * 12;
        float* dr = s_re + s * 12;
        float* di = s_im + s * 12;
        float4 a = __ldg((const float4*)(psi_re + g));
        float4 c = __ldg((const float4*)(psi_re + g + 4));
        float4 e = __ldg((const float4*)(psi_re + g + 8));
        *(float4*)(dr)     = a; *(float4*)(dr + 4) = c; *(float4*)(dr + 8) = e;
        a = __ldg((const float4*)(psi_im + g));
        c = __ldg((const float4*)(psi_im + g + 4));
        e = __ldg((const float4*)(psi_im + g + 8));
        *(float4*)(di)     = a; *(float4*)(di + 4) = c; *(float4*)(di + 8) = e;
    }
    __syncthreads();

    const int x2 = x2b + ty;
    const int site = (x0 << 15) | (x1 << 10) | (x2 << 5) | tx;

    float ar[12], ai[12];
#pragma unroll
    for (int k = 0; k < 12; k++) { ar[k] = 0.f; ai[k] = 0.f; }

    // Global neighbor indices for x0, x1 directions + backward U sites
    const int fw0 = (x0 == 31) ? site - (31 << 15) : site + (1 << 15);
    const int bw0 = (x0 == 0)  ? site + (31 << 15) : site - (1 << 15);
    const int fw1 = (x1 == 31) ? site - (31 << 10) : site + (1 << 10);
    const int bw1 = (x1 == 0)  ? site + (31 << 10) : site - (1 << 10);
    const int bw2 = (x2 == 0)  ? site + (31 << 5)  : site - (1 << 5);
    const int bw3 = (tx == 0)  ? site + 31 : site - 1;

    const size_t s36 = (size_t)site * 36;

    float Pr[12], Pi[12];

    // mu=0 (psi from global)
    load12g(psi_re + (size_t)fw0 * 12, Pr); load12g(psi_im + (size_t)fw0 * 12, Pi);
    term_core<0, false>(Pr, Pi, U_re + s36, U_im + s36, ar, ai);
    load12g(psi_re + (size_t)bw0 * 12, Pr); load12g(psi_im + (size_t)bw0 * 12, Pi);
    term_core<0, true >(Pr, Pi, U_re + (size_t)bw0 * 36, U_im + (size_t)bw0 * 36, ar, ai);

    // mu=1 (psi from global)
    load12g(psi_re + (size_t)fw1 * 12, Pr); load12g(psi_im + (size_t)fw1 * 12, Pi);
    term_core<1, false>(Pr, Pi, U_re + s36 + 9, U_im + s36 + 9, ar, ai);
    load12g(psi_re + (size_t)bw1 * 12, Pr); load12g(psi_im + (size_t)bw1 * 12, Pi);
    term_core<1, true >(Pr, Pi, U_re + (size_t)bw1 * 36 + 9, U_im + (size_t)bw1 * 36 + 9, ar, ai);

    // mu=2 (psi from smem; own row index in smem = ty+1)
    {
        int idx = ((ty + 2) * 32 + tx) * 12;           // x2 + 1
        load12s(s_re + idx, Pr); load12s(s_im + idx, Pi);
        term_core<2, false>(Pr, Pi, U_re + s36 + 18, U_im + s36 + 18, ar, ai);
        idx = (ty * 32 + tx) * 12;                     // x2 - 1
        load12s(s_re + idx, Pr); load12s(s_im + idx, Pi);
        term_core<2, true >(Pr, Pi, U_re + (size_t)bw2 * 36 + 18, U_im + (size_t)bw2 * 36 + 18, ar, ai);
    }

    // mu=3 (psi from smem, periodic in x3 within the full 32-line)
    {
        int idx = ((ty + 1) * 32 + ((tx + 1) & 31)) * 12;
        load12s(s_re + idx, Pr); load12s(s_im + idx, Pi);
        term_core<3, false>(Pr, Pi, U_re + s36 + 27, U_im + s36 + 27, ar, ai);
        idx = ((ty + 1) * 32 + ((tx + 31) & 31)) * 12;
        load12s(s_re + idx, Pr); load12s(s_im + idx, Pi);
        term_core<3, true >(Pr, Pi, U_re + (size_t)bw3 * 36 + 27, U_im + (size_t)bw3 * 36 + 27, ar, ai);
    }

    size_t o = (size_t)site * 12;
    float4 v;
    v.x = -0.5f * ar[0]; v.y = -0.5f * ar[1]; v.z = -0.5f * ar[2];  v.w = -0.5f * ar[3];
    *(float4*)(out_re + o)     = v;
    v.x = -0.5f * ar[4]; v.y = -0.5f * ar[5]; v.z = -0.5f * ar[6];  v.w = -0.5f * ar[7];
    *(float4*)(out_re + o + 4) = v;
    v.x = -0.5f * ar[8]; v.y = -0.5f * ar[9]; v.z = -0.5f * ar[10]; v.w = -0.5f * ar[11];
    *(float4*)(out_re + o + 8) = v;
    v.x = -0.5f * ai[0]; v.y = -0.5f * ai[1]; v.z = -0.5f * ai[2];  v.w = -0.5f * ai[3];
    *(float4*)(out_im + o)     = v;
    v.x = -0.5f * ai[4]; v.y = -0.5f * ai[5]; v.z = -0.5f * ai[6];  v.w = -0.5f * ai[7];
    *(float4*)(out_im + o + 4) = v;
    v.x = -0.5f * ai[8]; v.y = -0.5f * ai[9]; v.z = -0.5f * ai[10]; v.w = -0.5f * ai[11];
    *(float4*)(out_im + o + 8) = v;
}

extern "C" void kernel_launch(void* const* d_in, const int* in_sizes, int n_in,
                              void* d_out, int out_size) {
    const float* psi_re = (const float*)d_in[0];
    const float* psi_im = (const float*)d_in[1];
    const float* U_re   = (const float*)d_in[2];
    const float* U_im   = (const float*)d_in[3];
    float* out = (float*)d_out;
    float* out_re = out;
    float* out_im = out + (size_t)VOL * 12;

    wilson_dslash_kernel<<<VOL / 256, 256>>>(psi_re, psi_im, U_re, U_im, out_re, out_im);
}

// round 6
// speedup vs baseline: 1.0252x; 1.0252x over previous
#include <cuda_runtime.h>

// Wilson Dslash, 32^4, DeGrand-Rossi, half-spinor trick.
// R6 (= R5 resubmit after GPU-acquisition infra failure):
// R4's (x3=32, x2=8) smem-staged tile + __launch_bounds__(256,3)
// to fix the 2-blocks/SM register cliff (86 regs) seen in R4.

static constexpr int VOL = 1 << 20;

template<int A>
__device__ __forceinline__ void load9(const float* __restrict__ p, float* v) {
    if (A == 0) {
        float4 a = __ldg((const float4*)p);
        float4 b = __ldg((const float4*)(p + 4));
        v[0]=a.x; v[1]=a.y; v[2]=a.z; v[3]=a.w;
        v[4]=b.x; v[5]=b.y; v[6]=b.z; v[7]=b.w;
        v[8]=__ldg(p + 8);
    } else if (A == 4) {
        v[0]=__ldg(p);
        float2 c = __ldg((const float2*)(p + 1));
        float4 d = __ldg((const float4*)(p + 3));
        float2 e = __ldg((const float2*)(p + 7));
        v[1]=c.x; v[2]=c.y; v[3]=d.x; v[4]=d.y; v[5]=d.z; v[6]=d.w;
        v[7]=e.x; v[8]=e.y;
    } else if (A == 8) {
        float2 a = __ldg((const float2*)p);
        float4 b = __ldg((const float4*)(p + 2));
        float2 c = __ldg((const float2*)(p + 6));
        v[0]=a.x; v[1]=a.y; v[2]=b.x; v[3]=b.y; v[4]=b.z; v[5]=b.w;
        v[6]=c.x; v[7]=c.y; v[8]=__ldg(p + 8);
    } else {
        v[0]=__ldg(p);
        float4 b = __ldg((const float4*)(p + 1));
        float4 c = __ldg((const float4*)(p + 5));
        v[1]=b.x; v[2]=b.y; v[3]=b.z; v[4]=b.w;
        v[5]=c.x; v[6]=c.y; v[7]=c.z; v[8]=c.w;
    }
}

__device__ __forceinline__ void load12g(const float* __restrict__ p, float* v) {
    float4 a = __ldg((const float4*)p);
    float4 b = __ldg((const float4*)(p + 4));
    float4 c = __ldg((const float4*)(p + 8));
    v[0]=a.x; v[1]=a.y; v[2]=a.z;  v[3]=a.w;
    v[4]=b.x; v[5]=b.y; v[6]=b.z;  v[7]=b.w;
    v[8]=c.x; v[9]=c.y; v[10]=c.z; v[11]=c.w;
}

__device__ __forceinline__ void load12s(const float* p, float* v) {
    float4 a = *(const float4*)p;
    float4 b = *(const float4*)(p + 4);
    float4 c = *(const float4*)(p + 8);
    v[0]=a.x; v[1]=a.y; v[2]=a.z;  v[3]=a.w;
    v[4]=b.x; v[5]=b.y; v[6]=b.z;  v[7]=b.w;
    v[8]=c.x; v[9]=c.y; v[10]=c.z; v[11]=c.w;
}

template<int MU, bool DAG>
__device__ __forceinline__ void term_core(
    const float* Pr, const float* Pi,
    const float* __restrict__ ur, const float* __restrict__ ui,
    float* ar, float* ai)
{
    constexpr int A = (MU * 36) & 15;
    float Ur[9], Ui[9];
    load9<A>(ur, Ur);
    load9<A>(ui, Ui);

    float hr[6], hi[6];
#pragma unroll
    for (int c = 0; c < 3; c++) {
        float p0r = Pr[c],     p0i = Pi[c];
        float p1r = Pr[3 + c], p1i = Pi[3 + c];
        float p2r = Pr[6 + c], p2i = Pi[6 + c];
        float p3r = Pr[9 + c], p3i = Pi[9 + c];
        float h0r, h0i, h1r, h1i;
        if (MU == 0) {
            if (!DAG) { h0r = p0r + p3i; h0i = p0i - p3r; h1r = p1r + p2i; h1i = p1i - p2r; }
            else      { h0r = p0r - p3i; h0i = p0i + p3r; h1r = p1r - p2i; h1i = p1i + p2r; }
        } else if (MU == 1) {
            if (!DAG) { h0r = p0r + p3r; h0i = p0i + p3i; h1r = p1r - p2r; h1i = p1i - p2i; }
            else      { h0r = p0r - p3r; h0i = p0i - p3i; h1r = p1r + p2r; h1i = p1i + p2i; }
        } else if (MU == 2) {
            if (!DAG) { h0r = p0r + p2i; h0i = p0i - p2r; h1r = p1r - p3i; h1i = p1i + p3r; }
            else      { h0r = p0r - p2i; h0i = p0i + p2r; h1r = p1r + p3i; h1i = p1i - p3r; }
        } else {
            if (!DAG) { h0r = p0r - p2r; h0i = p0i - p2i; h1r = p1r - p3r; h1i = p1i - p3i; }
            else      { h0r = p0r + p2r; h0i = p0i + p2i; h1r = p1r + p3r; h1i = p1i + p3i; }
        }
        hr[c] = h0r; hi[c] = h0i; hr[3 + c] = h1r; hi[3 + c] = h1i;
    }

    float gr[6], gi[6];
#pragma unroll
    for (int s = 0; s < 2; s++) {
#pragma unroll
        for (int i = 0; i < 3; i++) {
            float rr = 0.f, ii = 0.f;
#pragma unroll
            for (int j = 0; j < 3; j++) {
                float urv, uiv;
                if (!DAG) { urv = Ur[i * 3 + j]; uiv = Ui[i * 3 + j]; }
                else      { urv = Ur[j * 3 + i]; uiv = -Ui[j * 3 + i]; }
                rr += urv * hr[s * 3 + j] - uiv * hi[s * 3 + j];
                ii += urv * hi[s * 3 + j] + uiv * hr[s * 3 + j];
            }
            gr[s * 3 + i] = rr; gi[s * 3 + i] = ii;
        }
    }

#pragma unroll
    for (int c = 0; c < 3; c++) {
        ar[c]     += gr[c];     ai[c]     += gi[c];
        ar[3 + c] += gr[3 + c]; ai[3 + c] += gi[3 + c];
        if (MU == 0) {
            if (!DAG) { ar[6+c] -= gi[3+c]; ai[6+c] += gr[3+c]; ar[9+c] -= gi[c]; ai[9+c] += gr[c]; }
            else      { ar[6+c] += gi[3+c]; ai[6+c] -= gr[3+c]; ar[9+c] += gi[c]; ai[9+c] -= gr[c]; }
        } else if (MU == 1) {
            if (!DAG) { ar[6+c] -= gr[3+c]; ai[6+c] -= gi[3+c]; ar[9+c] += gr[c]; ai[9+c] += gi[c]; }
            else      { ar[6+c] += gr[3+c]; ai[6+c] += gi[3+c]; ar[9+c] -= gr[c]; ai[9+c] -= gi[c]; }
        } else if (MU == 2) {
            if (!DAG) { ar[6+c] -= gi[c]; ai[6+c] += gr[c]; ar[9+c] += gi[3+c]; ai[9+c] -= gr[3+c]; }
            else      { ar[6+c] += gi[c]; ai[6+c] -= gr[c]; ar[9+c] -= gi[3+c]; ai[9+c] += gr[3+c]; }
        } else {
            if (!DAG) { ar[6+c] -= gr[c]; ai[6+c] -= gi[c]; ar[9+c] -= gr[3+c]; ai[9+c] -= gi[3+c]; }
            else      { ar[6+c] += gr[c]; ai[6+c] += gi[c]; ar[9+c] += gr[3+c]; ai[9+c] += gi[3+c]; }
        }
    }
}

__global__ void __launch_bounds__(256, 3) wilson_dslash_kernel(
    const float* __restrict__ psi_re, const float* __restrict__ psi_im,
    const float* __restrict__ U_re,   const float* __restrict__ U_im,
    float* __restrict__ out_re, float* __restrict__ out_im)
{
    __shared__ float s_re[10 * 32 * 12];
    __shared__ float s_im[10 * 32 * 12];

    const int tx = threadIdx.x & 31;       // x3
    const int ty = threadIdx.x >> 5;       // x2 within tile (0..7)
    const int b  = blockIdx.x;
    const int x2b = (b & 3) << 3;
    const int x1  = (b >> 2) & 31;
    const int x0  = b >> 7;

    // Stage psi rows x2b-1 .. x2b+8 (periodic)
    for (int s = threadIdx.x; s < 320; s += 256) {
        int row = s >> 5, x3s = s & 31;
        int x2s = (x2b + row + 31) & 31;
        size_t g = (size_t)((x0 << 15) | (x1 << 10) | (x2s << 5) | x3s) * 12;
        float* dr = s_re + s * 12;
        float* di = s_im + s * 12;
        float4 a = __ldg((const float4*)(psi_re + g));
        float4 c = __ldg((const float4*)(psi_re + g + 4));
        float4 e = __ldg((const float4*)(psi_re + g + 8));
        *(float4*)(dr)     = a; *(float4*)(dr + 4) = c; *(float4*)(dr + 8) = e;
        a = __ldg((const float4*)(psi_im + g));
        c = __ldg((const float4*)(psi_im + g + 4));
        e = __ldg((const float4*)(psi_im + g + 8));
        *(float4*)(di)     = a; *(float4*)(di + 4) = c; *(float4*)(di + 8) = e;
    }
    __syncthreads();

    const int x2 = x2b + ty;
    const int site = (x0 << 15) | (x1 << 10) | (x2 << 5) | tx;

    float ar[12], ai[12];
#pragma unroll
    for (int k = 0; k < 12; k++) { ar[k] = 0.f; ai[k] = 0.f; }

    const int fw0 = (x0 == 31) ? site - (31 << 15) : site + (1 << 15);
    const int bw0 = (x0 == 0)  ? site + (31 << 15) : site - (1 << 15);
    const int fw1 = (x1 == 31) ? site - (31 << 10) : site + (1 << 10);
    const int bw1 = (x1 == 0)  ? site + (31 << 10) : site - (1 << 10);
    const int bw2 = (x2 == 0)  ? site + (31 << 5)  : site - (1 << 5);
    const int bw3 = (tx == 0)  ? site + 31 : site - 1;

    const size_t s36 = (size_t)site * 36;

    float Pr[12], Pi[12];

    // mu=0 (global)
    load12g(psi_re + (size_t)fw0 * 12, Pr); load12g(psi_im + (size_t)fw0 * 12, Pi);
    term_core<0, false>(Pr, Pi, U_re + s36, U_im + s36, ar, ai);
    load12g(psi_re + (size_t)bw0 * 12, Pr); load12g(psi_im + (size_t)bw0 * 12, Pi);
    term_core<0, true >(Pr, Pi, U_re + (size_t)bw0 * 36, U_im + (size_t)bw0 * 36, ar, ai);

    // mu=1 (global)
    load12g(psi_re + (size_t)fw1 * 12, Pr); load12g(psi_im + (size_t)fw1 * 12, Pi);
    term_core<1, false>(Pr, Pi, U_re + s36 + 9, U_im + s36 + 9, ar, ai);
    load12g(psi_re + (size_t)bw1 * 12, Pr); load12g(psi_im + (size_t)bw1 * 12, Pi);
    term_core<1, true >(Pr, Pi, U_re + (size_t)bw1 * 36 + 9, U_im + (size_t)bw1 * 36 + 9, ar, ai);

    // mu=2 (smem)
    {
        int idx = ((ty + 2) * 32 + tx) * 12;
        load12s(s_re + idx, Pr); load12s(s_im + idx, Pi);
        term_core<2, false>(Pr, Pi, U_re + s36 + 18, U_im + s36 + 18, ar, ai);
        idx = (ty * 32 + tx) * 12;
        load12s(s_re + idx, Pr); load12s(s_im + idx, Pi);
        term_core<2, true >(Pr, Pi, U_re + (size_t)bw2 * 36 + 18, U_im + (size_t)bw2 * 36 + 18, ar, ai);
    }

    // mu=3 (smem, periodic x3)
    {
        int idx = ((ty + 1) * 32 + ((tx + 1) & 31)) * 12;
        load12s(s_re + idx, Pr); load12s(s_im + idx, Pi);
        term_core<3, false>(Pr, Pi, U_re + s36 + 27, U_im + s36 + 27, ar, ai);
        idx = ((ty + 1) * 32 + ((tx + 31) & 31)) * 12;
        load12s(s_re + idx, Pr); load12s(s_im + idx, Pi);
        term_core<3, true >(Pr, Pi, U_re + (size_t)bw3 * 36 + 27, U_im + (size_t)bw3 * 36 + 27, ar, ai);
    }

    size_t o = (size_t)site * 12;
    float4 v;
    v.x = -0.5f * ar[0]; v.y = -0.5f * ar[1]; v.z = -0.5f * ar[2];  v.w = -0.5f * ar[3];
    *(float4*)(out_re + o)     = v;
    v.x = -0.5f * ar[4]; v.y = -0.5f * ar[5]; v.z = -0.5f * ar[6];  v.w = -0.5f * ar[7];
    *(float4*)(out_re + o + 4) = v;
    v.x = -0.5f * ar[8]; v.y = -0.5f * ar[9]; v.z = -0.5f * ar[10]; v.w = -0.5f * ar[11];
    *(float4*)(out_re + o + 8) = v;
    v.x = -0.5f * ai[0]; v.y = -0.5f * ai[1]; v.z = -0.5f * ai[2];  v.w = -0.5f * ai[3];
    *(float4*)(out_im + o)     = v;
    v.x = -0.5f * ai[4]; v.y = -0.5f * ai[5]; v.z = -0.5f * ai[6];  v.w = -0.5f * ai[7];
    *(float4*)(out_im + o + 4) = v;
    v.x = -0.5f * ai[8]; v.y = -0.5f * ai[9]; v.z = -0.5f * ai[10]; v.w = -0.5f * ai[11];
    *(float4*)(out_im + o + 8) = v;
}

extern "C" void kernel_launch(void* const* d_in, const int* in_sizes, int n_in,
                              void* d_out, int out_size) {
    const float* psi_re = (const float*)d_in[0];
    const float* psi_im = (const float*)d_in[1];
    const float* U_re   = (const float*)d_in[2];
    const float* U_im   = (const float*)d_in[3];
    float* out = (float*)d_out;
    float* out_re = out;
    float* out_im = out + (size_t)VOL * 12;

    wilson_dslash_kernel<<<VOL / 256, 256>>>(psi_re, psi_im, U_re, U_im, out_re, out_im);
}

// round 7
// speedup vs baseline: 1.0316x; 1.0063x over previous
#include <cuda_runtime.h>

// Wilson Dslash, 32^4, DeGrand-Rossi, half-spinor trick.
// R7: R3 base (no smem) + warp-shuffle exchange for the x3 direction.
// Warp = one periodic x3 line, so psi[x±3] and U[x-3] move through the
// register file instead of L1/L2.

static constexpr int VOL = 1 << 20;

template<int A>
__device__ __forceinline__ void load9(const float* __restrict__ p, float* v) {
    if (A == 0) {
        float4 a = __ldg((const float4*)p);
        float4 b = __ldg((const float4*)(p + 4));
        v[0]=a.x; v[1]=a.y; v[2]=a.z; v[3]=a.w;
        v[4]=b.x; v[5]=b.y; v[6]=b.z; v[7]=b.w;
        v[8]=__ldg(p + 8);
    } else if (A == 4) {
        v[0]=__ldg(p);
        float2 c = __ldg((const float2*)(p + 1));
        float4 d = __ldg((const float4*)(p + 3));
        float2 e = __ldg((const float2*)(p + 7));
        v[1]=c.x; v[2]=c.y; v[3]=d.x; v[4]=d.y; v[5]=d.z; v[6]=d.w;
        v[7]=e.x; v[8]=e.y;
    } else if (A == 8) {
        float2 a = __ldg((const float2*)p);
        float4 b = __ldg((const float4*)(p + 2));
        float2 c = __ldg((const float2*)(p + 6));
        v[0]=a.x; v[1]=a.y; v[2]=b.x; v[3]=b.y; v[4]=b.z; v[5]=b.w;
        v[6]=c.x; v[7]=c.y; v[8]=__ldg(p + 8);
    } else {
        v[0]=__ldg(p);
        float4 b = __ldg((const float4*)(p + 1));
        float4 c = __ldg((const float4*)(p + 5));
        v[1]=b.x; v[2]=b.y; v[3]=b.z; v[4]=b.w;
        v[5]=c.x; v[6]=c.y; v[7]=c.z; v[8]=c.w;
    }
}

__device__ __forceinline__ void load12g(const float* __restrict__ p, float* v) {
    float4 a = __ldg((const float4*)p);
    float4 b = __ldg((const float4*)(p + 4));
    float4 c = __ldg((const float4*)(p + 8));
    v[0]=a.x; v[1]=a.y; v[2]=a.z;  v[3]=a.w;
    v[4]=b.x; v[5]=b.y; v[6]=b.z;  v[7]=b.w;
    v[8]=c.x; v[9]=c.y; v[10]=c.z; v[11]=c.w;
}

// g = U h  (DAG=false) or U^dagger h (DAG=true); h,g are 2 spins x 3 colors.
template<bool DAG>
__device__ __forceinline__ void matvec(
    const float* Ur, const float* Ui,
    const float* hr, const float* hi,
    float* gr, float* gi)
{
#pragma unroll
    for (int s = 0; s < 2; s++) {
#pragma unroll
        for (int i = 0; i < 3; i++) {
            float rr = 0.f, ii = 0.f;
#pragma unroll
            for (int j = 0; j < 3; j++) {
                float urv, uiv;
                if (!DAG) { urv = Ur[i * 3 + j]; uiv = Ui[i * 3 + j]; }
                else      { urv = Ur[j * 3 + i]; uiv = -Ui[j * 3 + i]; }
                rr += urv * hr[s * 3 + j] - uiv * hi[s * 3 + j];
                ii += urv * hi[s * 3 + j] + uiv * hr[s * 3 + j];
            }
            gr[s * 3 + i] = rr; gi[s * 3 + i] = ii;
        }
    }
}

// Full term for mu = 0,1,2 (psi fetched by caller into Pr/Pi).
template<int MU, bool DAG>
__device__ __forceinline__ void term_core(
    const float* Pr, const float* Pi,
    const float* __restrict__ ur, const float* __restrict__ ui,
    float* ar, float* ai)
{
    constexpr int A = (MU * 36) & 15;
    float Ur[9], Ui[9];
    load9<A>(ur, Ur);
    load9<A>(ui, Ui);

    float hr[6], hi[6];
#pragma unroll
    for (int c = 0; c < 3; c++) {
        float p0r = Pr[c],     p0i = Pi[c];
        float p1r = Pr[3 + c], p1i = Pi[3 + c];
        float p2r = Pr[6 + c], p2i = Pi[6 + c];
        float p3r = Pr[9 + c], p3i = Pi[9 + c];
        float h0r, h0i, h1r, h1i;
        if (MU == 0) {
            if (!DAG) { h0r = p0r + p3i; h0i = p0i - p3r; h1r = p1r + p2i; h1i = p1i - p2r; }
            else      { h0r = p0r - p3i; h0i = p0i + p3r; h1r = p1r - p2i; h1i = p1i + p2r; }
        } else if (MU == 1) {
            if (!DAG) { h0r = p0r + p3r; h0i = p0i + p3i; h1r = p1r - p2r; h1i = p1i - p2i; }
            else      { h0r = p0r - p3r; h0i = p0i - p3i; h1r = p1r + p2r; h1i = p1i + p2i; }
        } else {
            if (!DAG) { h0r = p0r + p2i; h0i = p0i - p2r; h1r = p1r - p3i; h1i = p1i + p3r; }
            else      { h0r = p0r - p2i; h0i = p0i + p2r; h1r = p1r + p3i; h1i = p1i - p3r; }
        }
        hr[c] = h0r; hi[c] = h0i; hr[3 + c] = h1r; hi[3 + c] = h1i;
    }

    float gr[6], gi[6];
    matvec<DAG>(Ur, Ui, hr, hi, gr, gi);

#pragma unroll
    for (int c = 0; c < 3; c++) {
        ar[c]     += gr[c];     ai[c]     += gi[c];
        ar[3 + c] += gr[3 + c]; ai[3 + c] += gi[3 + c];
        if (MU == 0) {
            if (!DAG) { ar[6+c] -= gi[3+c]; ai[6+c] += gr[3+c]; ar[9+c] -= gi[c]; ai[9+c] += gr[c]; }
            else      { ar[6+c] += gi[3+c]; ai[6+c] -= gr[3+c]; ar[9+c] += gi[c]; ai[9+c] -= gr[c]; }
        } else if (MU == 1) {
            if (!DAG) { ar[6+c] -= gr[3+c]; ai[6+c] -= gi[3+c]; ar[9+c] += gr[c]; ai[9+c] += gi[c]; }
            else      { ar[6+c] += gr[3+c]; ai[6+c] += gi[3+c]; ar[9+c] -= gr[c]; ai[9+c] -= gi[c]; }
        } else {
            if (!DAG) { ar[6+c] -= gi[c]; ai[6+c] += gr[c]; ar[9+c] += gi[3+c]; ai[9+c] -= gr[3+c]; }
            else      { ar[6+c] += gi[c]; ai[6+c] -= gr[c]; ar[9+c] -= gi[3+c]; ai[9+c] += gr[3+c]; }
        }
    }
}

__global__ void __launch_bounds__(128, 6) wilson_dslash_kernel(
    const float* __restrict__ psi_re, const float* __restrict__ psi_im,
    const float* __restrict__ U_re,   const float* __restrict__ U_im,
    float* __restrict__ out_re, float* __restrict__ out_im)
{
    const int site = blockIdx.x * blockDim.x + threadIdx.x;
    const int lane = threadIdx.x & 31;     // = x3 (warp is one periodic x3 line)
    const int x2 = (site >> 5) & 31, x1 = (site >> 10) & 31, x0 = site >> 15;
    const unsigned FULL = 0xffffffffu;
    const int upLane = (lane + 1) & 31;    // source for data of x3+1
    const int dnLane = (lane + 31) & 31;   // source for data of x3-1

    float ar[12], ai[12];
#pragma unroll
    for (int k = 0; k < 12; k++) { ar[k] = 0.f; ai[k] = 0.f; }

    const size_t s36 = (size_t)site * 36;

    // ================= mu = 3 via warp shuffles =================
    {
        // own psi + own U3
        float Or[12], Oi[12];
        load12g(psi_re + (size_t)site * 12, Or);
        load12g(psi_im + (size_t)site * 12, Oi);
        float U3r[9], U3i[9];
        load9<12>(U_re + s36 + 27, U3r);
        load9<12>(U_im + s36 + 27, U3i);

        // ---- forward: need proj_m3(psi[x+3]); neighbor computes its own projection.
        float hr[6], hi[6];
#pragma unroll
        for (int c = 0; c < 3; c++) {
            hr[c]     = Or[c]     - Or[6 + c];  hi[c]     = Oi[c]     - Oi[6 + c];
            hr[3 + c] = Or[3 + c] - Or[9 + c];  hi[3 + c] = Oi[3 + c] - Oi[9 + c];
        }
#pragma unroll
        for (int k = 0; k < 6; k++) {
            hr[k] = __shfl_sync(FULL, hr[k], upLane, 32);
            hi[k] = __shfl_sync(FULL, hi[k], upLane, 32);
        }
        float gr[6], gi[6];
        matvec<false>(U3r, U3i, hr, hi, gr, gi);
#pragma unroll
        for (int c = 0; c < 3; c++) {   // reconstruct mu=3, !DAG: r2=-g0, r3=-g1
            ar[c]     += gr[c];     ai[c]     += gi[c];
            ar[3 + c] += gr[3 + c]; ai[3 + c] += gi[3 + c];
            ar[6 + c] -= gr[c];     ai[6 + c] -= gi[c];
            ar[9 + c] -= gr[3 + c]; ai[9 + c] -= gi[3 + c];
        }

        // ---- backward: need U[x-3]^dag proj_p3(psi[x-3]); the x-3 thread owns both,
        // computes the full product, and we shuffle the 12-float result.
#pragma unroll
        for (int c = 0; c < 3; c++) {
            hr[c]     = Or[c]     + Or[6 + c];  hi[c]     = Oi[c]     + Oi[6 + c];
            hr[3 + c] = Or[3 + c] + Or[9 + c];  hi[3 + c] = Oi[3 + c] + Oi[9 + c];
        }
        matvec<true>(U3r, U3i, hr, hi, gr, gi);
#pragma unroll
        for (int k = 0; k < 6; k++) {
            gr[k] = __shfl_sync(FULL, gr[k], dnLane, 32);
            gi[k] = __shfl_sync(FULL, gi[k], dnLane, 32);
        }
#pragma unroll
        for (int c = 0; c < 3; c++) {   // reconstruct mu=3, DAG: r2=+g0, r3=+g1
            ar[c]     += gr[c];     ai[c]     += gi[c];
            ar[3 + c] += gr[3 + c]; ai[3 + c] += gi[3 + c];
            ar[6 + c] += gr[c];     ai[6 + c] += gi[c];
            ar[9 + c] += gr[3 + c]; ai[9 + c] += gi[3 + c];
        }
    }

    // ================= mu = 0,1,2 via global loads =================
    const int fw0 = (x0 == 31) ? site - (31 << 15) : site + (1 << 15);
    const int bw0 = (x0 == 0)  ? site + (31 << 15) : site - (1 << 15);
    const int fw1 = (x1 == 31) ? site - (31 << 10) : site + (1 << 10);
    const int bw1 = (x1 == 0)  ? site + (31 << 10) : site - (1 << 10);
    const int fw2 = (x2 == 31) ? site - (31 << 5)  : site + (1 << 5);
    const int bw2 = (x2 == 0)  ? site + (31 << 5)  : site - (1 << 5);

    float Pr[12], Pi[12];

    load12g(psi_re + (size_t)fw0 * 12, Pr); load12g(psi_im + (size_t)fw0 * 12, Pi);
    term_core<0, false>(Pr, Pi, U_re + s36, U_im + s36, ar, ai);
    load12g(psi_re + (size_t)bw0 * 12, Pr); load12g(psi_im + (size_t)bw0 * 12, Pi);
    term_core<0, true >(Pr, Pi, U_re + (size_t)bw0 * 36, U_im + (size_t)bw0 * 36, ar, ai);

    load12g(psi_re + (size_t)fw1 * 12, Pr); load12g(psi_im + (size_t)fw1 * 12, Pi);
    term_core<1, false>(Pr, Pi, U_re + s36 + 9, U_im + s36 + 9, ar, ai);
    load12g(psi_re + (size_t)bw1 * 12, Pr); load12g(psi_im + (size_t)bw1 * 12, Pi);
    term_core<1, true >(Pr, Pi, U_re + (size_t)bw1 * 36 + 9, U_im + (size_t)bw1 * 36 + 9, ar, ai);

    load12g(psi_re + (size_t)fw2 * 12, Pr); load12g(psi_im + (size_t)fw2 * 12, Pi);
    term_core<2, false>(Pr, Pi, U_re + s36 + 18, U_im + s36 + 18, ar, ai);
    load12g(psi_re + (size_t)bw2 * 12, Pr); load12g(psi_im + (size_t)bw2 * 12, Pi);
    term_core<2, true >(Pr, Pi, U_re + (size_t)bw2 * 36 + 18, U_im + (size_t)bw2 * 36 + 18, ar, ai);

    size_t o = (size_t)site * 12;
    float4 v;
    v.x = -0.5f * ar[0]; v.y = -0.5f * ar[1]; v.z = -0.5f * ar[2];  v.w = -0.5f * ar[3];
    *(float4*)(out_re + o)     = v;
    v.x = -0.5f * ar[4]; v.y = -0.5f * ar[5]; v.z = -0.5f * ar[6];  v.w = -0.5f * ar[7];
    *(float4*)(out_re + o + 4) = v;
    v.x = -0.5f * ar[8]; v.y = -0.5f * ar[9]; v.z = -0.5f * ar[10]; v.w = -0.5f * ar[11];
    *(float4*)(out_re + o + 8) = v;
    v.x = -0.5f * ai[0]; v.y = -0.5f * ai[1]; v.z = -0.5f * ai[2];  v.w = -0.5f * ai[3];
    *(float4*)(out_im + o)     = v;
    v.x = -0.5f * ai[4]; v.y = -0.5f * ai[5]; v.z = -0.5f * ai[6];  v.w = -0.5f * ai[7];
    *(float4*)(out_im + o + 4) = v;
    v.x = -0.5f * ai[8]; v.y = -0.5f * ai[9]; v.z = -0.5f * ai[10]; v.w = -0.5f * ai[11];
    *(float4*)(out_im + o + 8) = v;
}

extern "C" void kernel_launch(void* const* d_in, const int* in_sizes, int n_in,
                              void* d_out, int out_size) {
    const float* psi_re = (const float*)d_in[0];
    const float* psi_im = (const float*)d_in[1];
    const float* U_re   = (const float*)d_in[2];
    const float* U_im   = (const float*)d_in[3];
    float* out = (float*)d_out;
    float* out_re = out;
    float* out_im = out + (size_t)VOL * 12;

    wilson_dslash_kernel<<<VOL / 128, 128>>>(psi_re, psi_im, U_re, U_im, out_re, out_im);
}